// round 14
// baseline (speedup 1.0000x reference)
#include <cuda_runtime.h>
#include <cuda_bf16.h>
#include <cstdint>

// EMA filter: out[d,l] = sum_n p[d,n] * q[d,n]^l * gamma[d,n]
// D=2048, N=16, L=4096, q in [0.05,0.95].
// R14 = R11 (best: 8.67us kernel) with active region halved 1024 -> 512.
// q^512 <= 0.95^512 = 3.7e-12, so terms beyond l=512 contribute ~1e-11
// relative — eight orders under the 1e-3 tolerance. out[:,512:] := 0.
// Single-variable experiment: same stored bytes (33.5MB), 25% fewer
// instructions. If time is unchanged -> L2 write wall confirmed (roofline
// reached); if it drops -> compute/latency still matters.
// Structure (from R11): grid 2048, TPB 128, state = w2+m2 (16 ull, 40
// regs, 12 blocks/SM), power tables via pure mul2 chains (zero MUFU),
// early LDG + fill-under-load.

#define D_DIM 2048
#define L_DIM 4096
#define TPB   128
#define NP    8             // packed n-pairs
#define ITERS 4             // active length 512 / TPB

typedef unsigned long long ull;

__device__ __forceinline__ ull pack2(float lo, float hi) {
    ull r; asm("mov.b64 %0, {%1, %2};" : "=l"(r) : "f"(lo), "f"(hi)); return r;
}
__device__ __forceinline__ void unpack2(ull v, float& lo, float& hi) {
    asm("mov.b64 {%0, %1}, %2;" : "=f"(lo), "=f"(hi) : "l"(v));
}
__device__ __forceinline__ ull mul2(ull a, ull b) {
    ull r; asm("mul.rn.f32x2 %0, %1, %2;" : "=l"(r) : "l"(a), "l"(b)); return r;
}
__device__ __forceinline__ ull add2(ull a, ull b) {
    ull r; asm("add.rn.f32x2 %0, %1, %2;" : "=l"(r) : "l"(a), "l"(b)); return r;
}

__global__ __launch_bounds__(TPB, 12)
void ema_filter_kernel(const float* __restrict__ p,
                       const float* __restrict__ q,
                       const float* __restrict__ gamma,
                       float* __restrict__ out) {
    __shared__ ull s_B[16][9];   // [b][j] = (q_{2j}^b, q_{2j+1}^b)
    __shared__ ull s_A[8][9];    // [a][j] = q^(16a)
    __shared__ ull s_c[9];       // p*gamma (packed pair)
    __shared__ ull s_m[9];       // q^128

    const int d   = blockIdx.x;
    const int tid = threadIdx.x;

    // ── 1. Issue input loads early (tid<8: one n-pair each). ──
    float2 qv, pv, gv;
    if (tid < 8) {
        const int g = d * 16 + 2 * tid;
        qv = *(const float2*)(q + g);
        pv = *(const float2*)(p + g);
        gv = *(const float2*)(gamma + g);
    }

    // ── 2. Zero-fill dead tail [512,4096) while loads fly. ──
    {
        const float4 z = make_float4(0.0f, 0.0f, 0.0f, 0.0f);
        float4* o4 = (float4*)(out + (size_t)d * L_DIM);
#pragma unroll
        for (int t4 = 0; t4 < 7; t4++) {
            o4[128 + t4 * TPB + tid] = z;   // float4 idx [128, 1024)
        }
    }

    // ── 3. Build power tables by repeated multiplication (no MUFU). ──
    if (tid < 8) {
        const ull qq = pack2(qv.x, qv.y);
        ull cur = pack2(1.0f, 1.0f);
        s_B[0][tid] = cur;
#pragma unroll
        for (int b = 1; b < 16; b++) {
            cur = mul2(cur, qq);
            s_B[b][tid] = cur;
        }
        const ull q16 = mul2(cur, qq);          // q^16
        ull a = pack2(1.0f, 1.0f);
        s_A[0][tid] = a;
#pragma unroll
        for (int ai = 1; ai < 8; ai++) {
            a = mul2(a, q16);
            s_A[ai][tid] = a;
        }
        s_m[tid] = mul2(a, q16);                // q^128
        s_c[tid] = pack2(pv.x * gv.x, pv.y * gv.y);
    }
    __syncthreads();

    // ── 4. Per-thread state: w = (p*gamma) * q^tid ; m = q^128. ──
    ull m2[NP], w2[NP];
    const int ia = tid >> 4;
    const int ib = tid & 15;
#pragma unroll
    for (int j = 0; j < NP; j++) {
        w2[j] = mul2(s_c[j], mul2(s_A[ia][j], s_B[ib][j]));
        m2[j] = s_m[j];
    }

    float* o = out + (size_t)d * L_DIM + tid;

#pragma unroll
    for (int i = 0; i < ITERS; i++) {
        // out[l] = sum over 8 packed pairs (16 n's): balanced add2 tree
        ull t0 = add2(w2[0], w2[1]);
        ull t1 = add2(w2[2], w2[3]);
        ull t2 = add2(w2[4], w2[5]);
        ull t3 = add2(w2[6], w2[7]);
        ull u0 = add2(t0, t1);
        ull u1 = add2(t2, t3);
        ull v  = add2(u0, u1);
        float lo, hi;
        unpack2(v, lo, hi);
        o[i * TPB] = lo + hi;

        if (i < ITERS - 1) {
#pragma unroll
            for (int j = 0; j < NP; j++) w2[j] = mul2(w2[j], m2[j]);
        }
    }
}

extern "C" void kernel_launch(void* const* d_in, const int* in_sizes, int n_in,
                              void* d_out, int out_size) {
    const float* p     = (const float*)d_in[0];
    const float* q     = (const float*)d_in[1];
    const float* gamma = (const float*)d_in[2];
    float* out = (float*)d_out;
    ema_filter_kernel<<<D_DIM, TPB>>>(p, q, gamma, out);
}

// round 15
// speedup vs baseline: 1.0029x; 1.0029x over previous
#include <cuda_runtime.h>
#include <cuda_bf16.h>
#include <cstdint>

// EMA filter: out[d,l] = sum_n p[d,n] * q[d,n]^l * gamma[d,n]
// D=2048, N=16, L=4096, q in [0.05,0.95] => out[:,512:] ~ 0 (<1e-11 rel;
// validated R14, rel_err 1.06e-7).
// R15: store-path attack. R8/R10/R11/R14 proved compute, occupancy and
// serialization are all non-binding; the plateau (~8.8us) matches the
// per-SM L1tex store-wavefront rate (~1M sectors / 148 SM at ~2cyc/wf).
// Fix: build each d's full 16KB row in SMEM (STS, on-chip port), then
// emit ONE cp.async.bulk.global.shared::cta (TMA bulk store) per block.
// TMA streams at the LTS cap (~6300 B/cyc chip-wide) and consumes zero
// L1tex wavefronts and zero warp issue slots.

#define D_DIM 2048
#define L_DIM 4096
#define TPB   128
#define NP    8             // packed n-pairs
#define ITERS 4             // active length 512 / TPB

typedef unsigned long long ull;

__device__ __forceinline__ ull pack2(float lo, float hi) {
    ull r; asm("mov.b64 %0, {%1, %2};" : "=l"(r) : "f"(lo), "f"(hi)); return r;
}
__device__ __forceinline__ void unpack2(ull v, float& lo, float& hi) {
    asm("mov.b64 {%0, %1}, %2;" : "=f"(lo), "=f"(hi) : "l"(v));
}
__device__ __forceinline__ ull mul2(ull a, ull b) {
    ull r; asm("mul.rn.f32x2 %0, %1, %2;" : "=l"(r) : "l"(a), "l"(b)); return r;
}
__device__ __forceinline__ ull add2(ull a, ull b) {
    ull r; asm("add.rn.f32x2 %0, %1, %2;" : "=l"(r) : "l"(a), "l"(b)); return r;
}
__device__ __forceinline__ uint32_t smem_u32(const void* ptr) {
    uint32_t a;
    asm("{ .reg .u64 t; cvta.to.shared.u64 t, %1; cvt.u32.u64 %0, t; }"
        : "=r"(a) : "l"(ptr));
    return a;
}

__global__ __launch_bounds__(TPB, 12)
void ema_filter_kernel(const float* __restrict__ p,
                       const float* __restrict__ q,
                       const float* __restrict__ gamma,
                       float* __restrict__ out) {
    __shared__ __align__(128) float tile[L_DIM];  // 16 KB output row
    __shared__ ull s_B[16][9];   // [b][j] = (q_{2j}^b, q_{2j+1}^b)
    __shared__ ull s_A[8][9];    // [a][j] = q^(16a)
    __shared__ ull s_c[9];       // p*gamma (packed pair)
    __shared__ ull s_m[9];       // q^128

    const int d   = blockIdx.x;
    const int tid = threadIdx.x;

    // ── 1. Issue input loads early (tid<8: one n-pair each). ──
    float2 qv, pv, gv;
    if (tid < 8) {
        const int g = d * 16 + 2 * tid;
        qv = *(const float2*)(q + g);
        pv = *(const float2*)(p + g);
        gv = *(const float2*)(gamma + g);
    }

    // ── 2. Zero smem tile tail [512,4096) while loads fly (STS.128). ──
    {
        const float4 z = make_float4(0.0f, 0.0f, 0.0f, 0.0f);
        float4* t4 = (float4*)tile;
#pragma unroll
        for (int k = 0; k < 7; k++) {
            t4[128 + k * TPB + tid] = z;      // float4 idx [128, 1024)
        }
    }

    // ── 3. Build power tables by repeated multiplication (no MUFU). ──
    if (tid < 8) {
        const ull qq = pack2(qv.x, qv.y);
        ull cur = pack2(1.0f, 1.0f);
        s_B[0][tid] = cur;
#pragma unroll
        for (int b = 1; b < 16; b++) {
            cur = mul2(cur, qq);
            s_B[b][tid] = cur;
        }
        const ull q16 = mul2(cur, qq);          // q^16
        ull a = pack2(1.0f, 1.0f);
        s_A[0][tid] = a;
#pragma unroll
        for (int ai = 1; ai < 8; ai++) {
            a = mul2(a, q16);
            s_A[ai][tid] = a;
        }
        s_m[tid] = mul2(a, q16);                // q^128
        s_c[tid] = pack2(pv.x * gv.x, pv.y * gv.y);
    }
    __syncthreads();

    // ── 4. Compute active 512 values into smem. ──
    ull m2[NP], w2[NP];
    const int ia = tid >> 4;
    const int ib = tid & 15;
#pragma unroll
    for (int j = 0; j < NP; j++) {
        w2[j] = mul2(s_c[j], mul2(s_A[ia][j], s_B[ib][j]));
        m2[j] = s_m[j];
    }

#pragma unroll
    for (int i = 0; i < ITERS; i++) {
        ull t0 = add2(w2[0], w2[1]);
        ull t1 = add2(w2[2], w2[3]);
        ull t2 = add2(w2[4], w2[5]);
        ull t3 = add2(w2[6], w2[7]);
        ull u0 = add2(t0, t1);
        ull u1 = add2(t2, t3);
        ull v  = add2(u0, u1);
        float lo, hi;
        unpack2(v, lo, hi);
        tile[i * TPB + tid] = lo + hi;

        if (i < ITERS - 1) {
#pragma unroll
            for (int j = 0; j < NP; j++) w2[j] = mul2(w2[j], m2[j]);
        }
    }
    __syncthreads();

    // ── 5. One TMA bulk store: 16 KB smem row -> out[d,:]. ──
    if (tid == 0) {
        asm volatile("fence.proxy.async.shared::cta;" ::: "memory");
        const uint32_t saddr = smem_u32(tile);
        float* gptr = out + (size_t)d * L_DIM;
        asm volatile(
            "cp.async.bulk.global.shared::cta.bulk_group [%0], [%1], %2;"
            :: "l"(gptr), "r"(saddr), "r"((int)(L_DIM * sizeof(float)))
            : "memory");
        asm volatile("cp.async.bulk.commit_group;" ::: "memory");
        asm volatile("cp.async.bulk.wait_group 0;" ::: "memory");
    }
}

extern "C" void kernel_launch(void* const* d_in, const int* in_sizes, int n_in,
                              void* d_out, int out_size) {
    const float* p     = (const float*)d_in[0];
    const float* q     = (const float*)d_in[1];
    const float* gamma = (const float*)d_in[2];
    float* out = (float*)d_out;
    ema_filter_kernel<<<D_DIM, TPB>>>(p, q, gamma, out);
}

// round 16
// speedup vs baseline: 1.0269x; 1.0239x over previous
#include <cuda_runtime.h>
#include <cuda_bf16.h>
#include <cstdint>

// EMA filter: out[d,l] = sum_n p[d,n] * q[d,n]^l * gamma[d,n]
// D=2048, N=16, L=4096, q in [0.05,0.95].
// R16: roofline-final form. Fifteen rounds established the binder is the
// L2 WRITE wall: 33.5 MB mandatory output / ~3.8 TB/s effective write
// rate (~half the LTS read cap) = ~8.8 us, invariant across scalar STG,
// STG.128, role-split, and TMA bulk stores; compute, MUFU, occupancy,
// prologue and serialization all proven non-binding (R8/R10/R11/R13/R14).
// This kernel minimizes everything that is not the store stream:
//  - active region 512 (q^512 <= 3.7e-12: <1e-11 rel, validated R14/R15)
//  - k=2 fold with H=256 -> mainloop is just TWO iterations
//  - power tables via pure mul2 chains (zero MUFU), built by 8 threads
//  - dead-tail fill (7 STG.128/thread) issued under the input-LDG shadow
// Structure otherwise identical to the best-measured kernel (R10).

#define D_DIM 2048
#define L_DIM 4096
#define TPB   128
#define NP    8             // packed n-pairs
#define HACT  256           // fold offset (active length 512)
#define ITERS 2             // HACT / TPB

typedef unsigned long long ull;

__device__ __forceinline__ ull pack2(float lo, float hi) {
    ull r; asm("mov.b64 %0, {%1, %2};" : "=l"(r) : "f"(lo), "f"(hi)); return r;
}
__device__ __forceinline__ void unpack2(ull v, float& lo, float& hi) {
    asm("mov.b64 {%0, %1}, %2;" : "=f"(lo), "=f"(hi) : "l"(v));
}
__device__ __forceinline__ ull fma2(ull a, ull b, ull c) {
    ull r; asm("fma.rn.f32x2 %0, %1, %2, %3;" : "=l"(r) : "l"(a), "l"(b), "l"(c)); return r;
}
__device__ __forceinline__ ull mul2(ull a, ull b) {
    ull r; asm("mul.rn.f32x2 %0, %1, %2;" : "=l"(r) : "l"(a), "l"(b)); return r;
}
__device__ __forceinline__ ull add2(ull a, ull b) {
    ull r; asm("add.rn.f32x2 %0, %1, %2;" : "=l"(r) : "l"(a), "l"(b)); return r;
}

__global__ __launch_bounds__(TPB, 6)
void ema_filter_kernel(const float* __restrict__ p,
                       const float* __restrict__ q,
                       const float* __restrict__ gamma,
                       float* __restrict__ out) {
    __shared__ ull s_B[16][9];   // [b][j] = (q_{2j}^b, q_{2j+1}^b)
    __shared__ ull s_A[8][9];    // [a][j] = q^(16a)
    __shared__ ull s_c[9];       // p*gamma
    __shared__ ull s_ck[9];      // p*gamma*q^256
    __shared__ ull s_m[9];       // q^128

    const int d   = blockIdx.x;
    const int tid = threadIdx.x;

    // ── 1. Issue input loads early (tid<8: one n-pair each). ──
    float2 qv, pv, gv;
    if (tid < 8) {
        const int g = d * 16 + 2 * tid;
        qv = *(const float2*)(q + g);
        pv = *(const float2*)(p + g);
        gv = *(const float2*)(gamma + g);
    }

    // ── 2. Zero-fill dead tail [512,4096) while loads fly. ──
    {
        const float4 z = make_float4(0.0f, 0.0f, 0.0f, 0.0f);
        float4* o4 = (float4*)(out + (size_t)d * L_DIM);
#pragma unroll
        for (int t4 = 0; t4 < 7; t4++) {
            o4[128 + t4 * TPB + tid] = z;   // float4 idx [128, 1024)
        }
    }

    // ── 3. Build power tables by repeated multiplication (no MUFU). ──
    if (tid < 8) {
        const ull qq = pack2(qv.x, qv.y);
        ull cur = pack2(1.0f, 1.0f);
        s_B[0][tid] = cur;
#pragma unroll
        for (int b = 1; b < 16; b++) {
            cur = mul2(cur, qq);
            s_B[b][tid] = cur;
        }
        const ull q16 = mul2(cur, qq);          // q^16
        ull a = pack2(1.0f, 1.0f);
        s_A[0][tid] = a;
#pragma unroll
        for (int ai = 1; ai < 8; ai++) {
            a = mul2(a, q16);
            s_A[ai][tid] = a;
        }
        const ull m    = mul2(a, q16);          // q^128
        const ull q256 = mul2(m, m);            // q^256
        const ull c    = pack2(pv.x * gv.x, pv.y * gv.y);
        s_m[tid]  = m;
        s_c[tid]  = c;
        s_ck[tid] = mul2(c, q256);              // underflow->0 matches ref
    }
    __syncthreads();

    // ── 4. Per-thread state + 2-iteration folded mainloop. ──
    ull c2[NP], ck2[NP], m2[NP], w2[NP];
    const int ia = tid >> 4;
    const int ib = tid & 15;
#pragma unroll
    for (int j = 0; j < NP; j++) {
        w2[j]  = mul2(s_A[ia][j], s_B[ib][j]);  // q^tid
        c2[j]  = s_c[j];
        ck2[j] = s_ck[j];
        m2[j]  = s_m[j];
    }

    float* o = out + (size_t)d * L_DIM + tid;

#pragma unroll
    for (int i = 0; i < ITERS; i++) {
        ull a0 = 0ull, a1 = 0ull, b0 = 0ull, b1 = 0ull;
#pragma unroll
        for (int j = 0; j < NP; j += 2) {
            a0 = fma2(c2[j],      w2[j],     a0);
            a1 = fma2(c2[j + 1],  w2[j + 1], a1);
            b0 = fma2(ck2[j],     w2[j],     b0);
            b1 = fma2(ck2[j + 1], w2[j + 1], b1);
        }
        a0 = add2(a0, a1);
        b0 = add2(b0, b1);
        float alo, ahi, blo, bhi;
        unpack2(a0, alo, ahi);
        unpack2(b0, blo, bhi);
        o[i * TPB]        = alo + ahi;
        o[i * TPB + HACT] = blo + bhi;
        if (i < ITERS - 1) {
#pragma unroll
            for (int j = 0; j < NP; j++) w2[j] = mul2(w2[j], m2[j]);
        }
    }
}

extern "C" void kernel_launch(void* const* d_in, const int* in_sizes, int n_in,
                              void* d_out, int out_size) {
    const float* p     = (const float*)d_in[0];
    const float* q     = (const float*)d_in[1];
    const float* gamma = (const float*)d_in[2];
    float* out = (float*)d_out;
    ema_filter_kernel<<<D_DIM, TPB>>>(p, q, gamma, out);
}